// round 16
// baseline (speedup 1.0000x reference)
#include <cuda_runtime.h>

// ---------------------------------------------------------------------------
// AuxSeLoss: loss = mean(bce(out0,t)) + 0.4*mean(bce(out1,t)) + 0.2*mean(bce(out2, se_t))
// se_t[b,c] = 1 if any element of targets[b] falls in histc bin c (21 bins over [0,20]).
// Shapes: out0/out1/targets [16,21,256,256] f32, out2 [16,21] f32, output scalar f32.
//
// CONVERGED CONFIG (= R13, bench-verified best 47.9us; R15's unroll-3 looked
// faster under ncu, 46.5us, but regressed the replay-averaged bench -> keep
// unroll 2, the only confirmed sub-48 configuration):
//   - GRID=1184=16x74=148 SMs x 8 blocks, 256 thr, __launch_bounds__(256,8)
//     -> 32 regs -> exactly one resident wave (R8/R10: other residency
//     quantizations regressed).
//   - Ragged-edge rotation eIdx=(bInBatch+batch*9)%74 spreads the 12 extra-
//     iteration blocks per batch across SM slots (R12 win).
//   - lin/log accumulator split + log-product fusion (one LG2 per 4 elems).
//   - ALL streams __ldcs evict-first (R14: any caching policy regressed;
//     zero cross-replay L2 retention at 264MB working set).
//   - Single-kernel last-block finalize (threadfence + counter, cg publish).
// Epilogue-only delta: per-warp seen-flags folded via shared array instead of
// 8 shared-memory atomicOr (removes ATOMS serialization off the tail).
// ---------------------------------------------------------------------------

namespace {
constexpr int   NC            = 21;
constexpr int   NB            = 16;
constexpr long long HW        = 256LL * 256LL;
constexpr long long CHW       = (long long)NC * HW;     // 1376256
constexpr long long NTOT      = (long long)NB * CHW;    // 22020096
constexpr int   V4_PER_BATCH  = (int)(CHW / 4);         // 344064
constexpr int   BLK_PER_BATCH = 74;
constexpr int   GRID          = NB * BLK_PER_BATCH;     // 1184 = 148*8
constexpr int   THREADS       = 256;
constexpr int   NWARP         = THREADS / 32;
constexpr int   GROUPS        = V4_PER_BATCH / THREADS; // 1344 groups of 256 v4
constexpr int   FULL_ITERS    = GROUPS / BLK_PER_BATCH; // 18
constexpr int   EXTRA_BLKS    = GROUPS % BLK_PER_BATCH; // 12
static_assert(FULL_ITERS * BLK_PER_BATCH + EXTRA_BLKS == GROUPS, "");
constexpr float LOG2E         = 1.44269504088896340736f;
constexpr float LN2           = 0.69314718055994530942f;
}

__device__ float        g_part[GRID];
__device__ unsigned int g_flagp[GRID];
__device__ unsigned int g_count;          // zero at load; reset by finalizer

__global__ __launch_bounds__(THREADS, 8) void fused_kernel(
    const float4* __restrict__ o0,
    const float4* __restrict__ o1,
    const float4* __restrict__ tg,
    const float*  __restrict__ o2,
    float*        __restrict__ out) {

    __shared__ float        redS[NWARP];
    __shared__ unsigned int redSeen[NWARP];
    __shared__ int          isLastS;

    const int tid  = (int)threadIdx.x;
    const int lane = tid & 31;
    const int wid  = tid >> 5;

    const int blk      = (int)blockIdx.x;
    const int batch    = blk / BLK_PER_BATCH;
    const int bInBatch = blk - batch * BLK_PER_BATCH;
    // Rotated effective index: permutation of [0,74) per batch; spreads the
    // 12 extra-iteration slots (eIdx < 12) across different SMs per batch.
    const int eIdx     = (bInBatch + batch * 9) % BLK_PER_BATCH;
    const int myIters  = FULL_ITERS + (eIdx < EXTRA_BLKS ? 1 : 0);
    const int base     = batch * V4_PER_BATCH + eIdx * THREADS + tid;
    const int sStride  = BLK_PER_BATCH * THREADS;

    float lin0 = 0.0f, lg0 = 0.0f;   // out0: linear part, log2 part
    float lin1 = 0.0f, lg1 = 0.0f;   // out1
    unsigned int seen = 0u;
    const float inv_bw = 21.0f / 20.0f;   // 1 / ((n_classes-1)/n_classes)

    #pragma unroll 2
    for (int it = 0; it < myIters; ++it) {
        const int i = base + it * sStride;
        float4 a  = __ldcs(&o0[i]);
        float4 b4 = __ldcs(&o1[i]);
        float4 t4 = __ldcs(&tg[i]);

        // --- out0: product of (1+exp(-|x|)) factors, one LG2 per iteration ---
        {
            float e, p;
            e = exp2f(fabsf(a.x) * -LOG2E); p = 1.0f + e;
            e = exp2f(fabsf(a.y) * -LOG2E); p = fmaf(p, e, p);
            e = exp2f(fabsf(a.z) * -LOG2E); p = fmaf(p, e, p);
            e = exp2f(fabsf(a.w) * -LOG2E); p = fmaf(p, e, p);
            lg0 += __log2f(p);
            lin0 += (fmaxf(a.x, 0.0f) - a.x * t4.x)
                  + (fmaxf(a.y, 0.0f) - a.y * t4.y)
                  + (fmaxf(a.z, 0.0f) - a.z * t4.z)
                  + (fmaxf(a.w, 0.0f) - a.w * t4.w);
        }
        // --- out1 ---
        {
            float e, p;
            e = exp2f(fabsf(b4.x) * -LOG2E); p = 1.0f + e;
            e = exp2f(fabsf(b4.y) * -LOG2E); p = fmaf(p, e, p);
            e = exp2f(fabsf(b4.z) * -LOG2E); p = fmaf(p, e, p);
            e = exp2f(fabsf(b4.w) * -LOG2E); p = fmaf(p, e, p);
            lg1 += __log2f(p);
            lin1 += (fmaxf(b4.x, 0.0f) - b4.x * t4.x)
                  + (fmaxf(b4.y, 0.0f) - b4.y * t4.y)
                  + (fmaxf(b4.z, 0.0f) - b4.z * t4.z)
                  + (fmaxf(b4.w, 0.0f) - b4.w * t4.w);
        }

        float tv[4] = {t4.x, t4.y, t4.z, t4.w};
        #pragma unroll
        for (int k = 0; k < 4; ++k) {
            float v = tv[k];
            if (v >= 0.0f && v <= 20.0f) {            // histc drops out-of-range
                int idx = min((int)(v * inv_bw), NC - 1);   // trunc == floor for v>=0
                seen |= 1u << idx;
            }
        }
    }

    // s = bce0 + 0.4*bce1, with ln2 applied once to the log2 accumulators.
    float s = (lin0 + 0.4f * lin1) + LN2 * (lg0 + 0.4f * lg1);

    #pragma unroll
    for (int off = 16; off > 0; off >>= 1) {
        s    += __shfl_down_sync(0xffffffffu, s, off);
        seen |= __shfl_down_sync(0xffffffffu, seen, off);
    }
    if (lane == 0) {
        redS[wid]    = s;
        redSeen[wid] = seen;
    }
    __syncthreads();

    if (tid == 0) {
        s = redS[0];
        unsigned int fl = redSeen[0];
        #pragma unroll
        for (int w = 1; w < NWARP; ++w) { s += redS[w]; fl |= redSeen[w]; }
        // L2-coherent publish (no SM ever holds these lines stale in L1)
        __stcg(&g_part[blk], s);
        __stcg(&g_flagp[blk], fl);
        __threadfence();                               // order publishes before count
        unsigned int prev = atomicAdd(&g_count, 1u);
        isLastS = (prev == (unsigned int)(GRID - 1));
        if (isLastS) atomicExch(&g_count, 0u);         // reset for next replay
    }
    __syncthreads();
    if (!isLastS) return;

    // ---------------- last block: finalize ----------------
    __threadfence();   // acquire side of the counter handshake

    __shared__ unsigned int flagsF[NB];
    __shared__ double redD[NWARP];
    __shared__ float  redF[NWARP];
    if (tid < NB) flagsF[tid] = 0u;
    __syncthreads();

    double d01 = 0.0;
    #pragma unroll
    for (int i = tid; i < GRID; i += THREADS) {
        d01 += (double)__ldcg(&g_part[i]);
        unsigned int f = __ldcg(&g_flagp[i]);
        if (f) atomicOr(&flagsF[i / BLK_PER_BATCH], f);
    }
    #pragma unroll
    for (int off = 16; off > 0; off >>= 1)
        d01 += __shfl_down_sync(0xffffffffu, d01, off);
    if (lane == 0) redD[wid] = d01;
    __syncthreads();                  // also publishes flagsF

    // se BCE over ALL 336 out2 elements (strided; THREADS < 336)
    float v = 0.0f;
    for (int i = tid; i < NB * NC; i += THREADS) {
        int b = i / NC;
        int c = i - b * NC;
        float t = ((flagsF[b] >> c) & 1u) ? 1.0f : 0.0f;
        float x = o2[i];
        v += fmaxf(x, 0.0f) - x * t + log1pf(expf(-fabsf(x)));
    }
    #pragma unroll
    for (int off = 16; off > 0; off >>= 1)
        v += __shfl_down_sync(0xffffffffu, v, off);
    if (lane == 0) redF[wid] = v;
    __syncthreads();

    if (tid == 0) {
        double dd = 0.0; float vv = 0.0f;
        #pragma unroll
        for (int w = 0; w < NWARP; ++w) { dd += redD[w]; vv += redF[w]; }
        double loss01  = dd / (double)NTOT;
        double loss_se = (double)vv / (double)(NB * NC);
        out[0] = (float)(loss01 + 0.2 * loss_se);
    }
}

extern "C" void kernel_launch(void* const* d_in, const int* in_sizes, int n_in,
                              void* d_out, int out_size) {
    (void)in_sizes; (void)n_in; (void)out_size;
    const float4* o0 = (const float4*)d_in[0];
    const float4* o1 = (const float4*)d_in[1];
    const float*  o2 = (const float*) d_in[2];
    const float4* tg = (const float4*)d_in[3];

    fused_kernel<<<GRID, THREADS>>>(o0, o1, tg, o2, (float*)d_out);
}

// round 17
// speedup vs baseline: 1.1571x; 1.1571x over previous
#include <cuda_runtime.h>

// ---------------------------------------------------------------------------
// AuxSeLoss: loss = mean(bce(out0,t)) + 0.4*mean(bce(out1,t)) + 0.2*mean(bce(out2, se_t))
// se_t[b,c] = 1 if any element of targets[b] falls in histc bin c (21 bins over [0,20]).
// Shapes: out0/out1/targets [16,21,256,256] f32, out2 [16,21] f32, output scalar f32.
//
// FINAL = exact R13 source, the bench-verified session optimum (47.9us,
// ncu 48.2us, DRAM 70%, issue 47%, occ 93%). Two rounds (R15 epilogue tweak,
// R16 flag-fold tweak) proved that ANY perturbation of this source under the
// 32-reg cap destabilizes ptxas's hot-loop schedule (issue jumps to ~72%,
// +6us). Restored byte-identical.
// Config summary:
//   - GRID=1184=16x74=148 SMs x 8 blocks, 256 thr, __launch_bounds__(256,8)
//     -> 32 regs -> exactly one resident wave.
//   - Ragged-edge rotation eIdx=(bInBatch+batch*9)%74.
//   - lin/log accumulator split + log-product fusion (one LG2 per 4 elems).
//   - ALL streams __ldcs evict-first.
//   - Single-kernel last-block finalize (threadfence + counter, cg publish).
// ---------------------------------------------------------------------------

namespace {
constexpr int   NC            = 21;
constexpr int   NB            = 16;
constexpr long long HW        = 256LL * 256LL;
constexpr long long CHW       = (long long)NC * HW;     // 1376256
constexpr long long NTOT      = (long long)NB * CHW;    // 22020096
constexpr int   V4_PER_BATCH  = (int)(CHW / 4);         // 344064
constexpr int   BLK_PER_BATCH = 74;
constexpr int   GRID          = NB * BLK_PER_BATCH;     // 1184 = 148*8
constexpr int   THREADS       = 256;
constexpr int   NWARP         = THREADS / 32;
constexpr int   GROUPS        = V4_PER_BATCH / THREADS; // 1344 groups of 256 v4
constexpr int   FULL_ITERS    = GROUPS / BLK_PER_BATCH; // 18
constexpr int   EXTRA_BLKS    = GROUPS % BLK_PER_BATCH; // 12
static_assert(FULL_ITERS * BLK_PER_BATCH + EXTRA_BLKS == GROUPS, "");
constexpr float LOG2E         = 1.44269504088896340736f;
constexpr float LN2           = 0.69314718055994530942f;
}

__device__ float        g_part[GRID];
__device__ unsigned int g_flagp[GRID];
__device__ unsigned int g_count;          // zero at load; reset by finalizer

__global__ __launch_bounds__(THREADS, 8) void fused_kernel(
    const float4* __restrict__ o0,
    const float4* __restrict__ o1,
    const float4* __restrict__ tg,
    const float*  __restrict__ o2,
    float*        __restrict__ out) {

    __shared__ unsigned int flagS;
    __shared__ float redS[NWARP];
    __shared__ int   isLastS;

    const int tid  = (int)threadIdx.x;
    const int lane = tid & 31;
    const int wid  = tid >> 5;
    if (tid == 0) flagS = 0u;
    __syncthreads();

    const int blk      = (int)blockIdx.x;
    const int batch    = blk / BLK_PER_BATCH;
    const int bInBatch = blk - batch * BLK_PER_BATCH;
    // Rotated effective index: permutation of [0,74) per batch; spreads the
    // 12 extra-iteration slots (e < 12) across different SMs per batch.
    const int eIdx     = (bInBatch + batch * 9) % BLK_PER_BATCH;
    const int myIters  = FULL_ITERS + (eIdx < EXTRA_BLKS ? 1 : 0);
    const int base     = batch * V4_PER_BATCH + eIdx * THREADS + tid;
    const int sStride  = BLK_PER_BATCH * THREADS;

    float lin0 = 0.0f, lg0 = 0.0f;   // out0: linear part, log2 part
    float lin1 = 0.0f, lg1 = 0.0f;   // out1
    unsigned int seen = 0u;
    const float inv_bw = 21.0f / 20.0f;   // 1 / ((n_classes-1)/n_classes)

    #pragma unroll 2
    for (int it = 0; it < myIters; ++it) {
        const int i = base + it * sStride;
        float4 a  = __ldcs(&o0[i]);
        float4 b4 = __ldcs(&o1[i]);
        float4 t4 = __ldcs(&tg[i]);

        // --- out0: product of (1+exp(-|x|)) factors, one LG2 per iteration ---
        {
            float e, p;
            e = exp2f(fabsf(a.x) * -LOG2E); p = 1.0f + e;
            e = exp2f(fabsf(a.y) * -LOG2E); p = fmaf(p, e, p);
            e = exp2f(fabsf(a.z) * -LOG2E); p = fmaf(p, e, p);
            e = exp2f(fabsf(a.w) * -LOG2E); p = fmaf(p, e, p);
            lg0 += __log2f(p);
            lin0 += (fmaxf(a.x, 0.0f) - a.x * t4.x)
                  + (fmaxf(a.y, 0.0f) - a.y * t4.y)
                  + (fmaxf(a.z, 0.0f) - a.z * t4.z)
                  + (fmaxf(a.w, 0.0f) - a.w * t4.w);
        }
        // --- out1 ---
        {
            float e, p;
            e = exp2f(fabsf(b4.x) * -LOG2E); p = 1.0f + e;
            e = exp2f(fabsf(b4.y) * -LOG2E); p = fmaf(p, e, p);
            e = exp2f(fabsf(b4.z) * -LOG2E); p = fmaf(p, e, p);
            e = exp2f(fabsf(b4.w) * -LOG2E); p = fmaf(p, e, p);
            lg1 += __log2f(p);
            lin1 += (fmaxf(b4.x, 0.0f) - b4.x * t4.x)
                  + (fmaxf(b4.y, 0.0f) - b4.y * t4.y)
                  + (fmaxf(b4.z, 0.0f) - b4.z * t4.z)
                  + (fmaxf(b4.w, 0.0f) - b4.w * t4.w);
        }

        float tv[4] = {t4.x, t4.y, t4.z, t4.w};
        #pragma unroll
        for (int k = 0; k < 4; ++k) {
            float v = tv[k];
            if (v >= 0.0f && v <= 20.0f) {            // histc drops out-of-range
                int idx = min((int)(v * inv_bw), NC - 1);   // trunc == floor for v>=0
                seen |= 1u << idx;
            }
        }
    }

    // s = bce0 + 0.4*bce1, with ln2 applied once to the log2 accumulators.
    float s = (lin0 + 0.4f * lin1) + LN2 * (lg0 + 0.4f * lg1);

    #pragma unroll
    for (int off = 16; off > 0; off >>= 1) {
        s    += __shfl_down_sync(0xffffffffu, s, off);
        seen |= __shfl_down_sync(0xffffffffu, seen, off);
    }
    if (lane == 0) {
        redS[wid] = s;
        if (seen) atomicOr(&flagS, seen);
    }
    __syncthreads();

    if (tid == 0) {
        s = redS[0];
        #pragma unroll
        for (int w = 1; w < NWARP; ++w) s += redS[w];
        // L2-coherent publish (no SM ever holds these lines stale in L1)
        __stcg(&g_part[blk], s);
        __stcg(&g_flagp[blk], flagS);
        __threadfence();                               // order publishes before count
        unsigned int prev = atomicAdd(&g_count, 1u);
        isLastS = (prev == (unsigned int)(GRID - 1));
        if (isLastS) atomicExch(&g_count, 0u);         // reset for next replay
    }
    __syncthreads();
    if (!isLastS) return;

    // ---------------- last block: finalize ----------------
    __threadfence();   // acquire side of the counter handshake

    __shared__ unsigned int flagsF[NB];
    __shared__ double redD[NWARP];
    __shared__ float  redF[NWARP];
    if (tid < NB) flagsF[tid] = 0u;
    __syncthreads();

    double d01 = 0.0;
    #pragma unroll
    for (int i = tid; i < GRID; i += THREADS) {
        d01 += (double)__ldcg(&g_part[i]);
        unsigned int f = __ldcg(&g_flagp[i]);
        if (f) atomicOr(&flagsF[i / BLK_PER_BATCH], f);
    }
    #pragma unroll
    for (int off = 16; off > 0; off >>= 1)
        d01 += __shfl_down_sync(0xffffffffu, d01, off);
    if (lane == 0) redD[wid] = d01;
    __syncthreads();                  // also publishes flagsF

    // se BCE over ALL 336 out2 elements (strided; THREADS < 336)
    float v = 0.0f;
    for (int i = tid; i < NB * NC; i += THREADS) {
        int b = i / NC;
        int c = i - b * NC;
        float t = ((flagsF[b] >> c) & 1u) ? 1.0f : 0.0f;
        float x = o2[i];
        v += fmaxf(x, 0.0f) - x * t + log1pf(expf(-fabsf(x)));
    }
    #pragma unroll
    for (int off = 16; off > 0; off >>= 1)
        v += __shfl_down_sync(0xffffffffu, v, off);
    if (lane == 0) redF[wid] = v;
    __syncthreads();

    if (tid == 0) {
        double dd = 0.0; float vv = 0.0f;
        #pragma unroll
        for (int w = 0; w < NWARP; ++w) { dd += redD[w]; vv += redF[w]; }
        double loss01  = dd / (double)NTOT;
        double loss_se = (double)vv / (double)(NB * NC);
        out[0] = (float)(loss01 + 0.2 * loss_se);
    }
}

extern "C" void kernel_launch(void* const* d_in, const int* in_sizes, int n_in,
                              void* d_out, int out_size) {
    (void)in_sizes; (void)n_in; (void)out_size;
    const float4* o0 = (const float4*)d_in[0];
    const float4* o1 = (const float4*)d_in[1];
    const float*  o2 = (const float*) d_in[2];
    const float4* tg = (const float4*)d_in[3];

    fused_kernel<<<GRID, THREADS>>>(o0, o1, tg, o2, (float*)d_out);
}